// round 1
// baseline (speedup 1.0000x reference)
#include <cuda_runtime.h>
#include <cstdint>

#define NN 100000
#define HD 128

// ---------------- device scratch (no allocations allowed) ----------------
__device__ float g_degf[NN];
__device__ float g_dinv[NN];
__device__ float g_hp[(size_t)NN * HD];   // (h @ W) * dinv[row]
__device__ float g_acc[(size_t)NN * HD];  // scatter accumulator
__device__ float g_h1[(size_t)NN * HD];   // relu'd layer-1 output

// ---------------- small helpers: packed f32x2 math ----------------
__device__ __forceinline__ unsigned long long pack_dup(float v) {
    unsigned long long r;
    asm("mov.b64 %0, {%1, %1};" : "=l"(r) : "f"(v));
    return r;
}
__device__ __forceinline__ void fma2(unsigned long long& d, unsigned long long a,
                                     unsigned long long b) {
    asm("fma.rn.f32x2 %0, %1, %2, %3;" : "=l"(d) : "l"(a), "l"(b), "l"(d));
}
__device__ __forceinline__ float2 unpack2(unsigned long long v) {
    float2 f;
    asm("mov.b64 {%0, %1}, %2;" : "=f"(f.x), "=f"(f.y) : "l"(v));
    return f;
}

// ---------------- degree / normalization ----------------
__global__ void init_deg_kernel() {
    int n = blockIdx.x * blockDim.x + threadIdx.x;
    if (n < NN) g_degf[n] = 1.0f;  // self loop
}

__global__ void count_deg_kernel(const int* __restrict__ dst, int E) {
    int e = blockIdx.x * blockDim.x + threadIdx.x;
    if (e < E) atomicAdd(&g_degf[dst[e]], 1.0f);
}

__global__ void dinv_kernel() {
    int n = blockIdx.x * blockDim.x + threadIdx.x;
    if (n < NN) g_dinv[n] = rsqrtf(g_degf[n]);
}

// ---------------- zero the accumulator ----------------
__global__ void zero_acc_kernel() {
    int i = blockIdx.x * blockDim.x + threadIdx.x;  // float4 index
    if (i < NN * HD / 4) {
        *(float4*)&g_acc[(size_t)i * 4] = make_float4(0.f, 0.f, 0.f, 0.f);
    }
}

// ---------------- GEMM: g_hp = (A @ W) * dinv[row] ----------------
// BM=64 rows per block, full N=128 cols, BK=32 K-chunks.
// 256 threads as 16x16; each thread computes TM=4 rows x TN=8 cols
// using packed f32x2 FMA (2 cols per 64-bit accumulator).
#define BM 64
#define BK 32

__global__ void __launch_bounds__(256) gemm_scale_kernel(const float* __restrict__ A,
                                                         const float* __restrict__ W) {
    __shared__ unsigned long long As2[BK][BM];  // A values duplicated into f32x2
    __shared__ float Bs[BK][128];

    const int t = threadIdx.x;
    const int tx = t & 15;
    const int ty = t >> 4;
    const int rowBase = blockIdx.x * BM;

    unsigned long long acc2[4][4];
#pragma unroll
    for (int i = 0; i < 4; i++)
#pragma unroll
        for (int j = 0; j < 4; j++) acc2[i][j] = 0ULL;

    for (int kk = 0; kk < HD; kk += BK) {
        // --- load A tile (64 rows x 32 k), store duplicated f32x2, transposed ---
#pragma unroll
        for (int q = 0; q < 2; q++) {
            int idx = t + q * 256;       // 512 float4 total
            int r = idx >> 3;            // 0..63
            int kf = (idx & 7) << 2;     // 0,4,...,28
            int grow = rowBase + r;
            float4 v = make_float4(0.f, 0.f, 0.f, 0.f);
            if (grow < NN) v = *(const float4*)&A[(size_t)grow * HD + kk + kf];
            As2[kf + 0][r] = pack_dup(v.x);
            As2[kf + 1][r] = pack_dup(v.y);
            As2[kf + 2][r] = pack_dup(v.z);
            As2[kf + 3][r] = pack_dup(v.w);
        }
        // --- load W tile (32 k x 128 cols) ---
#pragma unroll
        for (int q = 0; q < 4; q++) {
            int idx = t + q * 256;       // 1024 float4 total
            int r = idx >> 5;            // 0..31
            int c = (idx & 31) << 2;     // 0..124
            *(float4*)&Bs[r][c] = *(const float4*)&W[(size_t)(kk + r) * HD + c];
        }
        __syncthreads();

#pragma unroll
        for (int k = 0; k < BK; k++) {
            ulonglong2 aa0 = *(const ulonglong2*)&As2[k][ty * 4];
            ulonglong2 aa1 = *(const ulonglong2*)&As2[k][ty * 4 + 2];
            const ulonglong2* bp = (const ulonglong2*)&Bs[k][tx * 8];
            ulonglong2 bb0 = bp[0];
            ulonglong2 bb1 = bp[1];
            unsigned long long a2[4] = {aa0.x, aa0.y, aa1.x, aa1.y};
            unsigned long long b2[4] = {bb0.x, bb0.y, bb1.x, bb1.y};
#pragma unroll
            for (int i = 0; i < 4; i++)
#pragma unroll
                for (int j = 0; j < 4; j++) fma2(acc2[i][j], a2[i], b2[j]);
        }
        __syncthreads();
    }

    // --- epilogue: scale by dinv[row], store ---
#pragma unroll
    for (int i = 0; i < 4; i++) {
        int row = rowBase + ty * 4 + i;
        if (row >= NN) continue;
        float s = g_dinv[row];
        float vals[8];
#pragma unroll
        for (int j = 0; j < 4; j++) {
            float2 f = unpack2(acc2[i][j]);
            vals[2 * j] = f.x * s;
            vals[2 * j + 1] = f.y * s;
        }
        float4 o0 = make_float4(vals[0], vals[1], vals[2], vals[3]);
        float4 o1 = make_float4(vals[4], vals[5], vals[6], vals[7]);
        *(float4*)&g_hp[(size_t)row * HD + tx * 8] = o0;
        *(float4*)&g_hp[(size_t)row * HD + tx * 8 + 4] = o1;
    }
}

// ---------------- edge scatter: acc[dst] += hp[src] ----------------
// One warp per edge; each lane moves one float4 and issues red.global.add.v4.f32
__global__ void __launch_bounds__(256) scatter_kernel(const int* __restrict__ src,
                                                      const int* __restrict__ dst, int E) {
    int g = blockIdx.x * blockDim.x + threadIdx.x;
    int e = g >> 5;
    int lane = g & 31;
    if (e >= E) return;
    int s = __ldg(&src[e]);
    int d = __ldg(&dst[e]);
    float4 v = *(const float4*)&g_hp[(size_t)s * HD + lane * 4];
    float* p = &g_acc[(size_t)d * HD + lane * 4];
    asm volatile("red.global.add.v4.f32 [%0], {%1, %2, %3, %4};"
                 :: "l"(p), "f"(v.x), "f"(v.y), "f"(v.z), "f"(v.w)
                 : "memory");
}

// ---------------- finalize: dst = [relu]( dinv[n] * (acc[n] + hp[n]) ) ----------------
__global__ void finalize_kernel(float* __restrict__ dst, int do_relu) {
    int i = blockIdx.x * blockDim.x + threadIdx.x;  // float4 index
    if (i >= NN * HD / 4) return;
    int n = i >> 5;  // 32 float4 per row
    float s = g_dinv[n];
    float4 a = *(const float4*)&g_acc[(size_t)i * 4];
    float4 h = *(const float4*)&g_hp[(size_t)i * 4];
    float4 o;
    o.x = s * (a.x + h.x);
    o.y = s * (a.y + h.y);
    o.z = s * (a.z + h.z);
    o.w = s * (a.w + h.w);
    if (do_relu) {
        o.x = fmaxf(o.x, 0.f);
        o.y = fmaxf(o.y, 0.f);
        o.z = fmaxf(o.z, 0.f);
        o.w = fmaxf(o.w, 0.f);
    }
    *(float4*)&dst[(size_t)i * 4] = o;
}

// ---------------- launch ----------------
extern "C" void kernel_launch(void* const* d_in, const int* in_sizes, int n_in,
                              void* d_out, int out_size) {
    const float* x  = (const float*)d_in[0];
    const int*   ei = (const int*)d_in[1];
    const float* W1 = (const float*)d_in[2];
    const float* W2 = (const float*)d_in[3];
    float* out = (float*)d_out;

    const int E = in_sizes[1] / 2;
    const int* src = ei;
    const int* dst = ei + E;

    float* h1_ptr = nullptr;
    cudaGetSymbolAddress((void**)&h1_ptr, g_h1);

    const int THR = 256;
    const int nodeBlocks = (NN + THR - 1) / THR;
    const int edgeBlocks = (E + THR - 1) / THR;
    const int vec4Blocks = (NN * HD / 4 + THR - 1) / THR;
    const int warpEdgeBlocks = (int)(((long long)E * 32 + THR - 1) / THR);
    const int gemmBlocks = (NN + BM - 1) / BM;

    // normalization coefficients
    init_deg_kernel<<<nodeBlocks, THR>>>();
    count_deg_kernel<<<edgeBlocks, THR>>>(dst, E);
    dinv_kernel<<<nodeBlocks, THR>>>();

    // ---- layer 1 ----
    gemm_scale_kernel<<<gemmBlocks, THR>>>(x, W1);       // g_hp = (x@W1)*dinv
    zero_acc_kernel<<<vec4Blocks, THR>>>();
    scatter_kernel<<<warpEdgeBlocks, THR>>>(src, dst, E);
    finalize_kernel<<<vec4Blocks, THR>>>(h1_ptr, 1);     // g_h1 = relu(dinv*(acc+hp))

    // ---- layer 2 ----
    gemm_scale_kernel<<<gemmBlocks, THR>>>(h1_ptr, W2);  // g_hp = (h1@W2)*dinv
    zero_acc_kernel<<<vec4Blocks, THR>>>();
    scatter_kernel<<<warpEdgeBlocks, THR>>>(src, dst, E);
    finalize_kernel<<<vec4Blocks, THR>>>(out, 0);        // out = dinv*(acc+hp)
}

// round 2
// speedup vs baseline: 1.0140x; 1.0140x over previous
#include <cuda_runtime.h>
#include <cstdint>

#define NN 100000
#define HD 128

// ---------------- device scratch (no allocations allowed) ----------------
__device__ float g_degf[NN];
__device__ float g_dinv[NN];
__device__ float g_hp[(size_t)NN * HD];   // (h @ W) * dinv[row]
__device__ float g_acc[(size_t)NN * HD];  // scatter accumulator
__device__ float g_h1[(size_t)NN * HD];   // relu'd layer-1 output

// ---------------- small helpers: packed f32x2 math ----------------
__device__ __forceinline__ unsigned long long pack_dup(float v) {
    unsigned long long r;
    asm("mov.b64 %0, {%1, %1};" : "=l"(r) : "f"(v));
    return r;
}
__device__ __forceinline__ void fma2(unsigned long long& d, unsigned long long a,
                                     unsigned long long b) {
    asm("fma.rn.f32x2 %0, %1, %2, %3;" : "=l"(d) : "l"(a), "l"(b), "l"(d));
}
__device__ __forceinline__ float2 unpack2(unsigned long long v) {
    float2 f;
    asm("mov.b64 {%0, %1}, %2;" : "=f"(f.x), "=f"(f.y) : "l"(v));
    return f;
}

// ---------------- degree / normalization ----------------
__global__ void init_deg_kernel() {
    int n = blockIdx.x * blockDim.x + threadIdx.x;
    if (n < NN) g_degf[n] = 1.0f;  // self loop
}

__global__ void count_deg_kernel(const int* __restrict__ dst, int E) {
    int e = blockIdx.x * blockDim.x + threadIdx.x;
    if (e < E) atomicAdd(&g_degf[dst[e]], 1.0f);
}

__global__ void dinv_kernel() {
    int n = blockIdx.x * blockDim.x + threadIdx.x;
    if (n < NN) g_dinv[n] = rsqrtf(g_degf[n]);
}

// ---------------- zero the accumulator ----------------
__global__ void zero_acc_kernel() {
    int i = blockIdx.x * blockDim.x + threadIdx.x;  // float4 index
    if (i < NN * HD / 4) {
        *(float4*)&g_acc[(size_t)i * 4] = make_float4(0.f, 0.f, 0.f, 0.f);
    }
}

// ---------------- GEMM: g_hp = (A @ W) * dinv[row] ----------------
// BM=64 rows per block, full N=128 cols, BK=32 K-chunks.
// 256 threads as 16x16; each thread computes TM=4 rows x TN=8 cols
// using packed f32x2 FMA (2 cols per 64-bit accumulator).
#define BM 64
#define BK 32

__global__ void __launch_bounds__(256) gemm_scale_kernel(const float* __restrict__ A,
                                                         const float* __restrict__ W) {
    __shared__ unsigned long long As2[BK][BM];  // A values duplicated into f32x2
    __shared__ float Bs[BK][128];

    const int t = threadIdx.x;
    const int tx = t & 15;
    const int ty = t >> 4;
    const int rowBase = blockIdx.x * BM;

    unsigned long long acc2[4][4];
#pragma unroll
    for (int i = 0; i < 4; i++)
#pragma unroll
        for (int j = 0; j < 4; j++) acc2[i][j] = 0ULL;

    for (int kk = 0; kk < HD; kk += BK) {
        // --- load A tile (64 rows x 32 k), store duplicated f32x2, transposed ---
#pragma unroll
        for (int q = 0; q < 2; q++) {
            int idx = t + q * 256;       // 512 float4 total
            int r = idx >> 3;            // 0..63
            int kf = (idx & 7) << 2;     // 0,4,...,28
            int grow = rowBase + r;
            float4 v = make_float4(0.f, 0.f, 0.f, 0.f);
            if (grow < NN) v = *(const float4*)&A[(size_t)grow * HD + kk + kf];
            As2[kf + 0][r] = pack_dup(v.x);
            As2[kf + 1][r] = pack_dup(v.y);
            As2[kf + 2][r] = pack_dup(v.z);
            As2[kf + 3][r] = pack_dup(v.w);
        }
        // --- load W tile (32 k x 128 cols) ---
#pragma unroll
        for (int q = 0; q < 4; q++) {
            int idx = t + q * 256;       // 1024 float4 total
            int r = idx >> 5;            // 0..31
            int c = (idx & 31) << 2;     // 0..124
            *(float4*)&Bs[r][c] = *(const float4*)&W[(size_t)(kk + r) * HD + c];
        }
        __syncthreads();

#pragma unroll
        for (int k = 0; k < BK; k++) {
            ulonglong2 aa0 = *(const ulonglong2*)&As2[k][ty * 4];
            ulonglong2 aa1 = *(const ulonglong2*)&As2[k][ty * 4 + 2];
            const ulonglong2* bp = (const ulonglong2*)&Bs[k][tx * 8];
            ulonglong2 bb0 = bp[0];
            ulonglong2 bb1 = bp[1];
            unsigned long long a2[4] = {aa0.x, aa0.y, aa1.x, aa1.y};
            unsigned long long b2[4] = {bb0.x, bb0.y, bb1.x, bb1.y};
#pragma unroll
            for (int i = 0; i < 4; i++)
#pragma unroll
                for (int j = 0; j < 4; j++) fma2(acc2[i][j], a2[i], b2[j]);
        }
        __syncthreads();
    }

    // --- epilogue: scale by dinv[row], store ---
#pragma unroll
    for (int i = 0; i < 4; i++) {
        int row = rowBase + ty * 4 + i;
        if (row >= NN) continue;
        float s = g_dinv[row];
        float vals[8];
#pragma unroll
        for (int j = 0; j < 4; j++) {
            float2 f = unpack2(acc2[i][j]);
            vals[2 * j] = f.x * s;
            vals[2 * j + 1] = f.y * s;
        }
        float4 o0 = make_float4(vals[0], vals[1], vals[2], vals[3]);
        float4 o1 = make_float4(vals[4], vals[5], vals[6], vals[7]);
        *(float4*)&g_hp[(size_t)row * HD + tx * 8] = o0;
        *(float4*)&g_hp[(size_t)row * HD + tx * 8 + 4] = o1;
    }
}

// ---------------- edge scatter: acc[dst] += hp[src] ----------------
// One warp per edge; each lane moves one float4 and issues red.global.add.v4.f32
__global__ void __launch_bounds__(256) scatter_kernel(const int* __restrict__ src,
                                                      const int* __restrict__ dst, int E) {
    int g = blockIdx.x * blockDim.x + threadIdx.x;
    int e = g >> 5;
    int lane = g & 31;
    if (e >= E) return;
    int s = __ldg(&src[e]);
    int d = __ldg(&dst[e]);
    float4 v = *(const float4*)&g_hp[(size_t)s * HD + lane * 4];
    float* p = &g_acc[(size_t)d * HD + lane * 4];
    asm volatile("red.global.add.v4.f32 [%0], {%1, %2, %3, %4};"
                 :: "l"(p), "f"(v.x), "f"(v.y), "f"(v.z), "f"(v.w)
                 : "memory");
}

// ---------------- finalize: dst = [relu]( dinv[n] * (acc[n] + hp[n]) ) ----------------
__global__ void finalize_kernel(float* __restrict__ dst, int do_relu) {
    int i = blockIdx.x * blockDim.x + threadIdx.x;  // float4 index
    if (i >= NN * HD / 4) return;
    int n = i >> 5;  // 32 float4 per row
    float s = g_dinv[n];
    float4 a = *(const float4*)&g_acc[(size_t)i * 4];
    float4 h = *(const float4*)&g_hp[(size_t)i * 4];
    float4 o;
    o.x = s * (a.x + h.x);
    o.y = s * (a.y + h.y);
    o.z = s * (a.z + h.z);
    o.w = s * (a.w + h.w);
    if (do_relu) {
        o.x = fmaxf(o.x, 0.f);
        o.y = fmaxf(o.y, 0.f);
        o.z = fmaxf(o.z, 0.f);
        o.w = fmaxf(o.w, 0.f);
    }
    *(float4*)&dst[(size_t)i * 4] = o;
}

// ---------------- launch ----------------
extern "C" void kernel_launch(void* const* d_in, const int* in_sizes, int n_in,
                              void* d_out, int out_size) {
    const float* x  = (const float*)d_in[0];
    const int*   ei = (const int*)d_in[1];
    const float* W1 = (const float*)d_in[2];
    const float* W2 = (const float*)d_in[3];
    float* out = (float*)d_out;

    const int E = in_sizes[1] / 2;
    const int* src = ei;
    const int* dst = ei + E;

    float* h1_ptr = nullptr;
    cudaGetSymbolAddress((void**)&h1_ptr, g_h1);

    const int THR = 256;
    const int nodeBlocks = (NN + THR - 1) / THR;
    const int edgeBlocks = (E + THR - 1) / THR;
    const int vec4Blocks = (NN * HD / 4 + THR - 1) / THR;
    const int warpEdgeBlocks = (int)(((long long)E * 32 + THR - 1) / THR);
    const int gemmBlocks = (NN + BM - 1) / BM;

    // normalization coefficients
    init_deg_kernel<<<nodeBlocks, THR>>>();
    count_deg_kernel<<<edgeBlocks, THR>>>(dst, E);
    dinv_kernel<<<nodeBlocks, THR>>>();

    // ---- layer 1 ----
    gemm_scale_kernel<<<gemmBlocks, THR>>>(x, W1);       // g_hp = (x@W1)*dinv
    zero_acc_kernel<<<vec4Blocks, THR>>>();
    scatter_kernel<<<warpEdgeBlocks, THR>>>(src, dst, E);
    finalize_kernel<<<vec4Blocks, THR>>>(h1_ptr, 1);     // g_h1 = relu(dinv*(acc+hp))

    // ---- layer 2 ----
    gemm_scale_kernel<<<gemmBlocks, THR>>>(h1_ptr, W2);  // g_hp = (h1@W2)*dinv
    zero_acc_kernel<<<vec4Blocks, THR>>>();
    scatter_kernel<<<warpEdgeBlocks, THR>>>(src, dst, E);
    finalize_kernel<<<vec4Blocks, THR>>>(out, 0);        // out = dinv*(acc+hp)
}

// round 3
// speedup vs baseline: 1.0158x; 1.0017x over previous
#include <cuda_runtime.h>
#include <cstdint>

#define NN 100000
#define HD 128

// ---------------- device scratch (no allocations allowed) ----------------
__device__ float g_degf[NN];
__device__ float g_dinv[NN];
__device__ float g_hp[(size_t)NN * HD];   // (h @ W) * dinv[row]
__device__ float g_acc[(size_t)NN * HD];  // scatter accumulator
__device__ float g_h1[(size_t)NN * HD];   // relu'd layer-1 output

// ---------------- small helpers: packed f32x2 math ----------------
__device__ __forceinline__ unsigned long long pack_dup(float v) {
    unsigned long long r;
    asm("mov.b64 %0, {%1, %1};" : "=l"(r) : "f"(v));
    return r;
}
__device__ __forceinline__ void fma2(unsigned long long& d, unsigned long long a,
                                     unsigned long long b) {
    asm("fma.rn.f32x2 %0, %1, %2, %3;" : "=l"(d) : "l"(a), "l"(b), "l"(d));
}
__device__ __forceinline__ float2 unpack2(unsigned long long v) {
    float2 f;
    asm("mov.b64 {%0, %1}, %2;" : "=f"(f.x), "=f"(f.y) : "l"(v));
    return f;
}

// ---------------- degree / normalization ----------------
__global__ void init_deg_kernel() {
    int n = blockIdx.x * blockDim.x + threadIdx.x;
    if (n < NN) g_degf[n] = 1.0f;  // self loop
}

__global__ void count_deg_kernel(const int* __restrict__ dst, int E) {
    int e = blockIdx.x * blockDim.x + threadIdx.x;
    if (e < E) atomicAdd(&g_degf[dst[e]], 1.0f);
}

__global__ void dinv_kernel() {
    int n = blockIdx.x * blockDim.x + threadIdx.x;
    if (n < NN) g_dinv[n] = rsqrtf(g_degf[n]);
}

// ---------------- zero the accumulator ----------------
__global__ void zero_acc_kernel() {
    int i = blockIdx.x * blockDim.x + threadIdx.x;  // float4 index
    if (i < NN * HD / 4) {
        *(float4*)&g_acc[(size_t)i * 4] = make_float4(0.f, 0.f, 0.f, 0.f);
    }
}

// ---------------- GEMM: g_hp = (A @ W) * dinv[row] ----------------
// BM=64 rows per block, full N=128 cols, BK=32 K-chunks.
// 256 threads as 16x16; each thread computes TM=4 rows x TN=8 cols
// using packed f32x2 FMA (2 cols per 64-bit accumulator).
#define BM 64
#define BK 32

__global__ void __launch_bounds__(256) gemm_scale_kernel(const float* __restrict__ A,
                                                         const float* __restrict__ W) {
    __shared__ unsigned long long As2[BK][BM];  // A values duplicated into f32x2
    __shared__ float Bs[BK][128];

    const int t = threadIdx.x;
    const int tx = t & 15;
    const int ty = t >> 4;
    const int rowBase = blockIdx.x * BM;

    unsigned long long acc2[4][4];
#pragma unroll
    for (int i = 0; i < 4; i++)
#pragma unroll
        for (int j = 0; j < 4; j++) acc2[i][j] = 0ULL;

    for (int kk = 0; kk < HD; kk += BK) {
        // --- load A tile (64 rows x 32 k), store duplicated f32x2, transposed ---
#pragma unroll
        for (int q = 0; q < 2; q++) {
            int idx = t + q * 256;       // 512 float4 total
            int r = idx >> 3;            // 0..63
            int kf = (idx & 7) << 2;     // 0,4,...,28
            int grow = rowBase + r;
            float4 v = make_float4(0.f, 0.f, 0.f, 0.f);
            if (grow < NN) v = *(const float4*)&A[(size_t)grow * HD + kk + kf];
            As2[kf + 0][r] = pack_dup(v.x);
            As2[kf + 1][r] = pack_dup(v.y);
            As2[kf + 2][r] = pack_dup(v.z);
            As2[kf + 3][r] = pack_dup(v.w);
        }
        // --- load W tile (32 k x 128 cols) ---
#pragma unroll
        for (int q = 0; q < 4; q++) {
            int idx = t + q * 256;       // 1024 float4 total
            int r = idx >> 5;            // 0..31
            int c = (idx & 31) << 2;     // 0..124
            *(float4*)&Bs[r][c] = *(const float4*)&W[(size_t)(kk + r) * HD + c];
        }
        __syncthreads();

#pragma unroll
        for (int k = 0; k < BK; k++) {
            ulonglong2 aa0 = *(const ulonglong2*)&As2[k][ty * 4];
            ulonglong2 aa1 = *(const ulonglong2*)&As2[k][ty * 4 + 2];
            const ulonglong2* bp = (const ulonglong2*)&Bs[k][tx * 8];
            ulonglong2 bb0 = bp[0];
            ulonglong2 bb1 = bp[1];
            unsigned long long a2[4] = {aa0.x, aa0.y, aa1.x, aa1.y};
            unsigned long long b2[4] = {bb0.x, bb0.y, bb1.x, bb1.y};
#pragma unroll
            for (int i = 0; i < 4; i++)
#pragma unroll
                for (int j = 0; j < 4; j++) fma2(acc2[i][j], a2[i], b2[j]);
        }
        __syncthreads();
    }

    // --- epilogue: scale by dinv[row], store ---
#pragma unroll
    for (int i = 0; i < 4; i++) {
        int row = rowBase + ty * 4 + i;
        if (row >= NN) continue;
        float s = g_dinv[row];
        float vals[8];
#pragma unroll
        for (int j = 0; j < 4; j++) {
            float2 f = unpack2(acc2[i][j]);
            vals[2 * j] = f.x * s;
            vals[2 * j + 1] = f.y * s;
        }
        float4 o0 = make_float4(vals[0], vals[1], vals[2], vals[3]);
        float4 o1 = make_float4(vals[4], vals[5], vals[6], vals[7]);
        *(float4*)&g_hp[(size_t)row * HD + tx * 8] = o0;
        *(float4*)&g_hp[(size_t)row * HD + tx * 8 + 4] = o1;
    }
}

// ---------------- edge scatter: acc[dst] += hp[src] ----------------
// One warp per edge; each lane moves one float4 and issues red.global.add.v4.f32
__global__ void __launch_bounds__(256) scatter_kernel(const int* __restrict__ src,
                                                      const int* __restrict__ dst, int E) {
    int g = blockIdx.x * blockDim.x + threadIdx.x;
    int e = g >> 5;
    int lane = g & 31;
    if (e >= E) return;
    int s = __ldg(&src[e]);
    int d = __ldg(&dst[e]);
    float4 v = *(const float4*)&g_hp[(size_t)s * HD + lane * 4];
    float* p = &g_acc[(size_t)d * HD + lane * 4];
    asm volatile("red.global.add.v4.f32 [%0], {%1, %2, %3, %4};"
                 :: "l"(p), "f"(v.x), "f"(v.y), "f"(v.z), "f"(v.w)
                 : "memory");
}

// ---------------- finalize: dst = [relu]( dinv[n] * (acc[n] + hp[n]) ) ----------------
__global__ void finalize_kernel(float* __restrict__ dst, int do_relu) {
    int i = blockIdx.x * blockDim.x + threadIdx.x;  // float4 index
    if (i >= NN * HD / 4) return;
    int n = i >> 5;  // 32 float4 per row
    float s = g_dinv[n];
    float4 a = *(const float4*)&g_acc[(size_t)i * 4];
    float4 h = *(const float4*)&g_hp[(size_t)i * 4];
    float4 o;
    o.x = s * (a.x + h.x);
    o.y = s * (a.y + h.y);
    o.z = s * (a.z + h.z);
    o.w = s * (a.w + h.w);
    if (do_relu) {
        o.x = fmaxf(o.x, 0.f);
        o.y = fmaxf(o.y, 0.f);
        o.z = fmaxf(o.z, 0.f);
        o.w = fmaxf(o.w, 0.f);
    }
    *(float4*)&dst[(size_t)i * 4] = o;
}

// ---------------- launch ----------------
extern "C" void kernel_launch(void* const* d_in, const int* in_sizes, int n_in,
                              void* d_out, int out_size) {
    const float* x  = (const float*)d_in[0];
    const int*   ei = (const int*)d_in[1];
    const float* W1 = (const float*)d_in[2];
    const float* W2 = (const float*)d_in[3];
    float* out = (float*)d_out;

    const int E = in_sizes[1] / 2;
    const int* src = ei;
    const int* dst = ei + E;

    float* h1_ptr = nullptr;
    cudaGetSymbolAddress((void**)&h1_ptr, g_h1);

    const int THR = 256;
    const int nodeBlocks = (NN + THR - 1) / THR;
    const int edgeBlocks = (E + THR - 1) / THR;
    const int vec4Blocks = (NN * HD / 4 + THR - 1) / THR;
    const int warpEdgeBlocks = (int)(((long long)E * 32 + THR - 1) / THR);
    const int gemmBlocks = (NN + BM - 1) / BM;

    // normalization coefficients
    init_deg_kernel<<<nodeBlocks, THR>>>();
    count_deg_kernel<<<edgeBlocks, THR>>>(dst, E);
    dinv_kernel<<<nodeBlocks, THR>>>();

    // ---- layer 1 ----
    gemm_scale_kernel<<<gemmBlocks, THR>>>(x, W1);       // g_hp = (x@W1)*dinv
    zero_acc_kernel<<<vec4Blocks, THR>>>();
    scatter_kernel<<<warpEdgeBlocks, THR>>>(src, dst, E);
    finalize_kernel<<<vec4Blocks, THR>>>(h1_ptr, 1);     // g_h1 = relu(dinv*(acc+hp))

    // ---- layer 2 ----
    gemm_scale_kernel<<<gemmBlocks, THR>>>(h1_ptr, W2);  // g_hp = (h1@W2)*dinv
    zero_acc_kernel<<<vec4Blocks, THR>>>();
    scatter_kernel<<<warpEdgeBlocks, THR>>>(src, dst, E);
    finalize_kernel<<<vec4Blocks, THR>>>(out, 0);        // out = dinv*(acc+hp)
}